// round 3
// baseline (speedup 1.0000x reference)
#include <cuda_runtime.h>

#define NTOK 32768
#define KCB  8192
#define DIM  256
#define BM 128
#define BN 128
#define BKD 16

__device__ float  g_zz[NTOK];
__device__ float  g_ww[KCB];
__device__ int    g_idx[NTOK];
__device__ float  g_count[KCB];
__device__ float  g_avg[KCB * DIM];
__device__ double g_commit;
__device__ double g_nsum;

__global__ void k_init() {
    unsigned i = blockIdx.x * blockDim.x + threadIdx.x;
    if (i < (unsigned)(KCB * DIM)) g_avg[i] = 0.0f;
    if (i < (unsigned)KCB)         g_count[i] = 0.0f;
    if (i == 0) { g_commit = 0.0; g_nsum = 0.0; }
}

__global__ void k_norms(const float* __restrict__ z, const float* __restrict__ emb) {
    int w    = (blockIdx.x * blockDim.x + threadIdx.x) >> 5;
    int lane = threadIdx.x & 31;
    if (w >= NTOK + KCB) return;
    const float4* r4 = (const float4*)((w < NTOK) ? (z + (size_t)w * DIM)
                                                  : (emb + (size_t)(w - NTOK) * DIM));
    double s = 0.0;
#pragma unroll
    for (int i = 0; i < 2; i++) {
        float4 v = r4[lane + 32 * i];
        s += (double)v.x * v.x + (double)v.y * v.y + (double)v.z * v.z + (double)v.w * v.w;
    }
#pragma unroll
    for (int o = 16; o; o >>= 1) s += __shfl_down_sync(0xffffffffu, s, o);
    if (lane == 0) {
        if (w < NTOK) g_zz[w] = (float)s; else g_ww[w - NTOK] = (float)s;
    }
}

__device__ __forceinline__ void stage_store(float* A, float* B, int lrow, int lkp,
                                            float4 a0, float4 a1, float4 b0, float4 b1) {
    *(float2*)(A + (lkp    ) * 2 * BM + 2 * lrow)        = make_float2(a0.x, a0.y);
    *(float2*)(A + (lkp + 1) * 2 * BM + 2 * lrow)        = make_float2(a0.z, a0.w);
    *(float2*)(A + (lkp    ) * 2 * BM + 2 * (lrow + 64)) = make_float2(a1.x, a1.y);
    *(float2*)(A + (lkp + 1) * 2 * BM + 2 * (lrow + 64)) = make_float2(a1.z, a1.w);
    *(float2*)(B + (lkp    ) * 2 * BN + 2 * lrow)        = make_float2(b0.x, b0.y);
    *(float2*)(B + (lkp + 1) * 2 * BN + 2 * lrow)        = make_float2(b0.z, b0.w);
    *(float2*)(B + (lkp    ) * 2 * BN + 2 * (lrow + 64)) = make_float2(b1.x, b1.y);
    *(float2*)(B + (lkp + 1) * 2 * BN + 2 * (lrow + 64)) = make_float2(b1.z, b1.w);
}

__global__ __launch_bounds__(256, 1)
void k_argmin(const float* __restrict__ z, const float* __restrict__ emb) {
    __shared__ __align__(16) float Ap[2][(BKD / 2) * 2 * BM];
    __shared__ __align__(16) float Bp[2][(BKD / 2) * 2 * BN];

    int tid = threadIdx.x;
    int tx = tid & 15, ty = tid >> 4;
    int x = tx * 8, y = ty * 8;
    int m0 = blockIdx.x * BM;

    float zzr[8];
#pragma unroll
    for (int i = 0; i < 8; i++) zzr[i] = g_zz[m0 + y + i];

    float bestv[8]; int besti[8];
#pragma unroll
    for (int i = 0; i < 8; i++) { bestv[i] = __int_as_float(0x7f800000); besti[i] = 0; }

    int lrow = tid >> 2;
    int lcg  = (tid & 3) * 4;
    int lkp  = lcg >> 1;

    for (int nt = 0; nt < KCB / BN; ++nt) {
        int n0 = nt * BN;
        unsigned long long acc[8][8];
#pragma unroll
        for (int i = 0; i < 8; i++)
#pragma unroll
            for (int j = 0; j < 8; j++) acc[i][j] = 0ULL;

        float4 a0 = *(const float4*)(z   + (size_t)(m0 + lrow     ) * DIM + lcg);
        float4 a1 = *(const float4*)(z   + (size_t)(m0 + lrow + 64) * DIM + lcg);
        float4 b0 = *(const float4*)(emb + (size_t)(n0 + lrow     ) * DIM + lcg);
        float4 b1 = *(const float4*)(emb + (size_t)(n0 + lrow + 64) * DIM + lcg);
        stage_store(Ap[0], Bp[0], lrow, lkp, a0, a1, b0, b1);
        __syncthreads();

        for (int kt = 0; kt < DIM / BKD; ++kt) {
            int cur = kt & 1;
            if (kt + 1 < DIM / BKD) {
                int d0 = (kt + 1) * BKD + lcg;
                a0 = *(const float4*)(z   + (size_t)(m0 + lrow     ) * DIM + d0);
                a1 = *(const float4*)(z   + (size_t)(m0 + lrow + 64) * DIM + d0);
                b0 = *(const float4*)(emb + (size_t)(n0 + lrow     ) * DIM + d0);
                b1 = *(const float4*)(emb + (size_t)(n0 + lrow + 64) * DIM + d0);
            }
            const float* A = Ap[cur];
            const float* B = Bp[cur];
#pragma unroll
            for (int kp = 0; kp < BKD / 2; ++kp) {
                unsigned long long a2[8], b2[8];
#pragma unroll
                for (int i = 0; i < 8; i += 2) {
                    ulonglong2 v = *(const ulonglong2*)(A + kp * 2 * BM + 2 * (y + i));
                    a2[i] = v.x; a2[i + 1] = v.y;
                }
#pragma unroll
                for (int j = 0; j < 8; j += 2) {
                    ulonglong2 v = *(const ulonglong2*)(B + kp * 2 * BN + 2 * (x + j));
                    b2[j] = v.x; b2[j + 1] = v.y;
                }
#pragma unroll
                for (int i = 0; i < 8; i++)
#pragma unroll
                    for (int j = 0; j < 8; j++)
                        asm("fma.rn.f32x2 %0, %1, %2, %0;"
                            : "+l"(acc[i][j]) : "l"(a2[i]), "l"(b2[j]));
            }
            if (kt + 1 < DIM / BKD)
                stage_store(Ap[cur ^ 1], Bp[cur ^ 1], lrow, lkp, a0, a1, b0, b1);
            __syncthreads();
        }

        float wwv[8];
#pragma unroll
        for (int j = 0; j < 8; j++) wwv[j] = g_ww[n0 + x + j];
#pragma unroll
        for (int i = 0; i < 8; i++)
#pragma unroll
            for (int j = 0; j < 8; j++) {
                float lo  = __uint_as_float((unsigned)(acc[i][j] & 0xffffffffULL));
                float hi  = __uint_as_float((unsigned)(acc[i][j] >> 32));
                float dot = lo + hi;
                float dist = (zzr[i] - 2.0f * dot) + wwv[j];
                if (dist < bestv[i]) { bestv[i] = dist; besti[i] = n0 + x + j; }
            }
    }

#pragma unroll
    for (int i = 0; i < 8; i++) {
        float v = bestv[i]; int ix = besti[i];
#pragma unroll
        for (int o = 8; o; o >>= 1) {
            float ov = __shfl_down_sync(0xffffffffu, v, o, 16);
            int   oi = __shfl_down_sync(0xffffffffu, ix, o, 16);
            if (ov < v || (ov == v && oi < ix)) { v = ov; ix = oi; }
        }
        if (tx == 0) g_idx[m0 + y + i] = ix;
    }
}

__global__ void k_scatter(const float* __restrict__ z, const float* __restrict__ emb,
                          float* __restrict__ out) {
    int row  = blockIdx.x * 8 + (threadIdx.x >> 5);
    int lane = threadIdx.x & 31;
    int k = g_idx[row];
    const float4* zr = (const float4*)(z   + (size_t)row * DIM);
    const float4* wr = (const float4*)(emb + (size_t)k  * DIM);
    float4*       oq = (float4*)(out + (size_t)row * DIM);

    float cs = 0.0f;
#pragma unroll
    for (int h = 0; h < 2; h++) {
        int c = lane + 32 * h;
        float4 zv = zr[c];
        float4 wv = wr[c];
        float4 o;
        o.x = zv.x + (wv.x - zv.x);
        o.y = zv.y + (wv.y - zv.y);
        o.z = zv.z + (wv.z - zv.z);
        o.w = zv.w + (wv.w - zv.w);
        oq[c] = o;
        float dx = zv.x - wv.x, dy = zv.y - wv.y, dz = zv.z - wv.z, dw = zv.w - wv.w;
        cs += dx * dx + dy * dy + dz * dz + dw * dw;
        float* ar = &g_avg[(size_t)k * DIM + 4 * c];
        atomicAdd(ar + 0, zv.x); atomicAdd(ar + 1, zv.y);
        atomicAdd(ar + 2, zv.z); atomicAdd(ar + 3, zv.w);
    }
#pragma unroll
    for (int o = 16; o; o >>= 1) cs += __shfl_down_sync(0xffffffffu, cs, o);

    __shared__ float sred[8];
    if (lane == 0) {
        sred[threadIdx.x >> 5] = cs;
        atomicAdd(&g_count[k], 1.0f);
        out[(size_t)NTOK * DIM + 1 + row] = (float)k;
    }
    __syncthreads();
    if (threadIdx.x == 0) {
        double bs = 0.0;
#pragma unroll
        for (int i = 0; i < 8; i++) bs += (double)sred[i];
        atomicAdd(&g_commit, bs);
    }
}

__global__ void k_nsum(const float* __restrict__ ema_count) {
    __shared__ double sd[1024];
    int t = threadIdx.x;
    double s = 0.0;
    for (int k = t; k < KCB; k += 1024)
        s += (double)(0.99f * ema_count[k] + 0.01f * g_count[k]);
    sd[t] = s;
    __syncthreads();
    for (int o = 512; o; o >>= 1) {
        if (t < o) sd[t] += sd[t + o];
        __syncthreads();
    }
    if (t == 0) g_nsum = sd[0];
}

__global__ void k_final(const float* __restrict__ ema_count,
                        const float* __restrict__ ema_avg,
                        float* __restrict__ out) {
    size_t i = (size_t)blockIdx.x * 256 + threadIdx.x;
    if (i >= (size_t)KCB * DIM) return;
    int k = (int)(i >> 8);
    float cnt = 0.99f * ema_count[k] + 0.01f * g_count[k];
    float avg = 0.99f * ema_avg[i]   + 0.01f * g_avg[i];
    float nn  = (float)g_nsum;
    float cluster = (cnt + 1e-5f) / (nn + 0.08192f) * nn;
    const size_t oE = (size_t)NTOK * DIM + 1 + NTOK;
    const size_t oC = oE + (size_t)KCB * DIM;
    const size_t oA = oC + KCB;
    out[oE + i] = avg / cluster;
    out[oA + i] = avg;
    if ((i & 255) == 0) out[oC + k] = cnt;
    if (i == 0)
        out[(size_t)NTOK * DIM] =
            (float)(0.25 * g_commit / (double)((size_t)NTOK * DIM));
}

extern "C" void kernel_launch(void* const* d_in, const int* in_sizes, int n_in,
                              void* d_out, int out_size) {
    const float* z_e       = (const float*)d_in[0];
    const float* embedding = (const float*)d_in[1];
    const float* ema_count = (const float*)d_in[2];
    const float* ema_avg   = (const float*)d_in[3];
    float* out = (float*)d_out;

    k_init<<<(KCB * DIM + 255) / 256, 256>>>();
    k_norms<<<(NTOK + KCB) / 8, 256>>>(z_e, embedding);
    k_argmin<<<NTOK / BM, 256>>>(z_e, embedding);
    k_scatter<<<NTOK / 8, 256>>>(z_e, embedding, out);
    k_nsum<<<1, 1024>>>(ema_count);
    k_final<<<(KCB * DIM + 255) / 256, 256>>>(ema_count, ema_avg, out);
}

// round 8
// speedup vs baseline: 1.3165x; 1.3165x over previous
#include <cuda_runtime.h>

#define NTOK 32768
#define KCB  8192
#define DIM  256
#define BM 128
#define BN 128
#define BKD 16

__device__ float  g_zz[NTOK];
__device__ float  g_ww[KCB];
__device__ int    g_idx[NTOK];
__device__ float  g_count[KCB];
__device__ float  g_avg[KCB * DIM];
__device__ double g_commit;
__device__ double g_nsum;

__global__ void k_init_a() {
    unsigned i = blockIdx.x * blockDim.x + threadIdx.x;
    if (i < (unsigned)(KCB * DIM)) g_avg[i] = 0.0f;
}

__global__ void k_init_b() {
    unsigned i = blockIdx.x * blockDim.x + threadIdx.x;
    if (i < (unsigned)KCB) g_count[i] = 0.0f;
    if (i == 0) { g_commit = 0.0; g_nsum = 0.0; }
}

__global__ void k_norms(const float* __restrict__ z, const float* __restrict__ emb) {
    int w    = (blockIdx.x * blockDim.x + threadIdx.x) >> 5;
    int lane = threadIdx.x & 31;
    if (w >= NTOK + KCB) return;
    const float4* r4 = (const float4*)((w < NTOK) ? (z + (size_t)w * DIM)
                                                  : (emb + (size_t)(w - NTOK) * DIM));
    double s = 0.0;
#pragma unroll
    for (int i = 0; i < 2; i++) {
        float4 v = r4[lane + 32 * i];
        s += (double)v.x * v.x + (double)v.y * v.y + (double)v.z * v.z + (double)v.w * v.w;
    }
#pragma unroll
    for (int o = 16; o; o >>= 1) s += __shfl_down_sync(0xffffffffu, s, o);
    if (lane == 0) {
        if (w < NTOK) g_zz[w] = (float)s; else g_ww[w - NTOK] = (float)s;
    }
}

// ---------------------------------------------------------------------------
// distance GEMM + fused argmin.
// f32x2 pairs along N: acc[i][j2] = (dot(i, 2j2), dot(i, 2j2+1)), fp32 exact.
// A duplicated in smem (a,a) so FFMA2 operands come straight from LDS.128.
// ---------------------------------------------------------------------------
__global__ __launch_bounds__(256, 1)
void k_argmin(const float* __restrict__ z, const float* __restrict__ emb) {
    __shared__ __align__(16) float Ad[2][BKD][2 * BM];  // [d][2m+e], duplicated
    __shared__ __align__(16) float Bs[2][BKD][BN];      // [d][n]

    int tid = threadIdx.x;
    int tx = tid & 15, ty = tid >> 4;
    int x = tx * 8, y = ty * 8;       // 8 codes, 8 tokens per thread
    int m0 = blockIdx.x * BM;

    int sr = tid >> 1;                // staging row (0..127)
    int sc = (tid & 1) * 8;           // staging d-offset (0 or 8)

    float zzr[8];
#pragma unroll
    for (int i = 0; i < 8; i++) zzr[i] = g_zz[m0 + y + i];

    float bestv[8]; int besti[8];
#pragma unroll
    for (int i = 0; i < 8; i++) { bestv[i] = __int_as_float(0x7f800000); besti[i] = 0; }

    const float* zrow0 = z   + (size_t)(m0 + sr) * DIM + sc;

    for (int nt = 0; nt < KCB / BN; ++nt) {
        int n0 = nt * BN;
        const float* brow0 = emb + (size_t)(n0 + sr) * DIM + sc;

        unsigned long long acc[8][4];
#pragma unroll
        for (int i = 0; i < 8; i++)
#pragma unroll
            for (int j = 0; j < 4; j++) acc[i][j] = 0ULL;

        // stage 0
        float4 u = *(const float4*)(zrow0);
        float4 v = *(const float4*)(zrow0 + 4);
        float4 p = *(const float4*)(brow0);
        float4 q = *(const float4*)(brow0 + 4);
        {
            float* A0 = &Ad[0][sc][2 * sr];
            *(float2*)(A0 + 0 * 2 * BM) = make_float2(u.x, u.x);
            *(float2*)(A0 + 1 * 2 * BM) = make_float2(u.y, u.y);
            *(float2*)(A0 + 2 * 2 * BM) = make_float2(u.z, u.z);
            *(float2*)(A0 + 3 * 2 * BM) = make_float2(u.w, u.w);
            *(float2*)(A0 + 4 * 2 * BM) = make_float2(v.x, v.x);
            *(float2*)(A0 + 5 * 2 * BM) = make_float2(v.y, v.y);
            *(float2*)(A0 + 6 * 2 * BM) = make_float2(v.z, v.z);
            *(float2*)(A0 + 7 * 2 * BM) = make_float2(v.w, v.w);
            float* B0 = &Bs[0][sc][sr];
            B0[0 * BN] = p.x; B0[1 * BN] = p.y; B0[2 * BN] = p.z; B0[3 * BN] = p.w;
            B0[4 * BN] = q.x; B0[5 * BN] = q.y; B0[6 * BN] = q.z; B0[7 * BN] = q.w;
        }
        __syncthreads();

        for (int kt = 0; kt < DIM / BKD; ++kt) {
            int cur = kt & 1;
            if (kt + 1 < DIM / BKD) {
                int db = (kt + 1) * BKD;
                u = *(const float4*)(zrow0 + db);
                v = *(const float4*)(zrow0 + db + 4);
                p = *(const float4*)(brow0 + db);
                q = *(const float4*)(brow0 + db + 4);
            }
#pragma unroll
            for (int d = 0; d < BKD; ++d) {
                const float* ar = &Ad[cur][d][2 * y];
                const float* br = &Bs[cur][d][x];
                unsigned long long a2[8], b2[4];
#pragma unroll
                for (int i = 0; i < 4; i++) {
                    ulonglong2 t = *(const ulonglong2*)(ar + 4 * i);
                    a2[2 * i] = t.x; a2[2 * i + 1] = t.y;
                }
#pragma unroll
                for (int j = 0; j < 2; j++) {
                    ulonglong2 t = *(const ulonglong2*)(br + 4 * j);
                    b2[2 * j] = t.x; b2[2 * j + 1] = t.y;
                }
#pragma unroll
                for (int i = 0; i < 8; i++)
#pragma unroll
                    for (int j = 0; j < 4; j++)
                        asm("fma.rn.f32x2 %0, %1, %2, %0;"
                            : "+l"(acc[i][j]) : "l"(a2[i]), "l"(b2[j]));
            }
            if (kt + 1 < DIM / BKD) {
                int nx = cur ^ 1;
                float* A0 = &Ad[nx][sc][2 * sr];
                *(float2*)(A0 + 0 * 2 * BM) = make_float2(u.x, u.x);
                *(float2*)(A0 + 1 * 2 * BM) = make_float2(u.y, u.y);
                *(float2*)(A0 + 2 * 2 * BM) = make_float2(u.z, u.z);
                *(float2*)(A0 + 3 * 2 * BM) = make_float2(u.w, u.w);
                *(float2*)(A0 + 4 * 2 * BM) = make_float2(v.x, v.x);
                *(float2*)(A0 + 5 * 2 * BM) = make_float2(v.y, v.y);
                *(float2*)(A0 + 6 * 2 * BM) = make_float2(v.z, v.z);
                *(float2*)(A0 + 7 * 2 * BM) = make_float2(v.w, v.w);
                float* B0 = &Bs[nx][sc][sr];
                B0[0 * BN] = p.x; B0[1 * BN] = p.y; B0[2 * BN] = p.z; B0[3 * BN] = p.w;
                B0[4 * BN] = q.x; B0[5 * BN] = q.y; B0[6 * BN] = q.z; B0[7 * BN] = q.w;
            }
            __syncthreads();
        }

        // epilogue: dist = (zz - 2*dot) + ww, ascending n, strict <
        float wwv[8];
        *(float4*)&wwv[0] = *(const float4*)&g_ww[n0 + x];
        *(float4*)&wwv[4] = *(const float4*)&g_ww[n0 + x + 4];
#pragma unroll
        for (int i = 0; i < 8; i++)
#pragma unroll
            for (int j = 0; j < 4; j++) {
                float lo = __uint_as_float((unsigned)(acc[i][j] & 0xffffffffULL));
                float hi = __uint_as_float((unsigned)(acc[i][j] >> 32));
                float dl = (zzr[i] - 2.0f * lo) + wwv[2 * j];
                float dh = (zzr[i] - 2.0f * hi) + wwv[2 * j + 1];
                if (dl < bestv[i]) { bestv[i] = dl; besti[i] = n0 + x + 2 * j; }
                if (dh < bestv[i]) { bestv[i] = dh; besti[i] = n0 + x + 2 * j + 1; }
            }
    }

#pragma unroll
    for (int i = 0; i < 8; i++) {
        float v = bestv[i]; int ix = besti[i];
#pragma unroll
        for (int o = 8; o; o >>= 1) {
            float ov = __shfl_down_sync(0xffffffffu, v, o, 16);
            int   oi = __shfl_down_sync(0xffffffffu, ix, o, 16);
            if (ov < v || (ov == v && oi < ix)) { v = ov; ix = oi; }
        }
        if (tx == 0) g_idx[m0 + y + i] = ix;
    }
}

__global__ void k_scatter(const float* __restrict__ z, const float* __restrict__ emb,
                          float* __restrict__ out) {
    int row  = blockIdx.x * 8 + (threadIdx.x >> 5);
    int lane = threadIdx.x & 31;
    int k = g_idx[row];
    const float4* zr = (const float4*)(z   + (size_t)row * DIM);
    const float4* wr = (const float4*)(emb + (size_t)k  * DIM);
    float4*       oq = (float4*)(out + (size_t)row * DIM);

    float cs = 0.0f;
#pragma unroll
    for (int h = 0; h < 2; h++) {
        int c = lane + 32 * h;
        float4 zv = zr[c];
        float4 wv = wr[c];
        float4 o;
        o.x = zv.x + (wv.x - zv.x);
        o.y = zv.y + (wv.y - zv.y);
        o.z = zv.z + (wv.z - zv.z);
        o.w = zv.w + (wv.w - zv.w);
        oq[c] = o;
        float dx = zv.x - wv.x, dy = zv.y - wv.y, dz = zv.z - wv.z, dw = zv.w - wv.w;
        cs += dx * dx + dy * dy + dz * dz + dw * dw;
        float* ar = &g_avg[(size_t)k * DIM + 4 * c];
        atomicAdd(ar + 0, zv.x); atomicAdd(ar + 1, zv.y);
        atomicAdd(ar + 2, zv.z); atomicAdd(ar + 3, zv.w);
    }
#pragma unroll
    for (int o = 16; o; o >>= 1) cs += __shfl_down_sync(0xffffffffu, cs, o);

    __shared__ float sred[8];
    if (lane == 0) {
        sred[threadIdx.x >> 5] = cs;
        atomicAdd(&g_count[k], 1.0f);
        out[(size_t)NTOK * DIM + 1 + row] = (float)k;
    }
    __syncthreads();
    if (threadIdx.x == 0) {
        double bs = 0.0;
#pragma unroll
        for (int i = 0; i < 8; i++) bs += (double)sred[i];
        atomicAdd(&g_commit, bs);
    }
}

__global__ void k_nsum(const float* __restrict__ ema_count) {
    __shared__ double sd[1024];
    int t = threadIdx.x;
    double s = 0.0;
    for (int k = t; k < KCB; k += 1024)
        s += (double)(0.99f * ema_count[k] + 0.01f * g_count[k]);
    sd[t] = s;
    __syncthreads();
    for (int o = 512; o; o >>= 1) {
        if (t < o) sd[t] += sd[t + o];
        __syncthreads();
    }
    if (t == 0) g_nsum = sd[0];
}

__global__ void k_final(const float* __restrict__ ema_count,
                        const float* __restrict__ ema_avg,
                        float* __restrict__ out) {
    size_t i = (size_t)blockIdx.x * 256 + threadIdx.x;
    if (i >= (size_t)KCB * DIM) return;
    int k = (int)(i >> 8);
    float cnt = 0.99f * ema_count[k] + 0.01f * g_count[k];
    float avg = 0.99f * ema_avg[i]   + 0.01f * g_avg[i];
    float nn  = (float)g_nsum;
    float cluster = (cnt + 1e-5f) / (nn + 0.08192f) * nn;
    const size_t oE = (size_t)NTOK * DIM + 1 + NTOK;
    const size_t oC = oE + (size_t)KCB * DIM;
    const size_t oA = oC + KCB;
    out[oE + i] = avg / cluster;
    out[oA + i] = avg;
    if ((i & 255) == 0) out[oC + k] = cnt;
    if (i == 0)
        out[(size_t)NTOK * DIM] =
            (float)(0.25 * g_commit / (double)((size_t)NTOK * DIM));
}

extern "C" void kernel_launch(void* const* d_in, const int* in_sizes, int n_in,
                              void* d_out, int out_size) {
    const float* z_e       = (const float*)d_in[0];
    const float* embedding = (const float*)d_in[1];
    const float* ema_count = (const float*)d_in[2];
    const float* ema_avg   = (const float*)d_in[3];
    float* out = (float*)d_out;

    k_init_a<<<(KCB * DIM + 255) / 256, 256>>>();
    k_init_b<<<(KCB + 255) / 256, 256>>>();
    k_norms<<<(NTOK + KCB) / 8, 256>>>(z_e, embedding);
    k_argmin<<<NTOK / BM, 256>>>(z_e, embedding);   // 4th launch -> profiled slot
    k_scatter<<<NTOK / 8, 256>>>(z_e, embedding, out);
    k_nsum<<<1, 1024>>>(ema_count);
    k_final<<<(KCB * DIM + 255) / 256, 256>>>(ema_count, ema_avg, out);
}

// round 17
// speedup vs baseline: 1.5368x; 1.1673x over previous
#include <cuda_runtime.h>

#define NTOK 32768
#define KCB  8192
#define DIM  256
#define BM 256
#define BN 128
#define BKD 8
#define AROW 576   /* 16 groups x 36 words (32 data + 4 pad) */
#define BROW 144   /* 4 groups x 36 words */

__device__ float  g_zz[NTOK];
__device__ float  g_ww[KCB];
__device__ int    g_idx[NTOK];
__device__ float  g_count[KCB];
__device__ float  g_avg[KCB * DIM];
__device__ double g_commit;
__device__ double g_nsum;

__global__ void k_init_a() {
    unsigned i = blockIdx.x * blockDim.x + threadIdx.x;
    if (i < (unsigned)(KCB * DIM)) g_avg[i] = 0.0f;
}

__global__ void k_init_b() {
    unsigned i = blockIdx.x * blockDim.x + threadIdx.x;
    if (i < (unsigned)KCB) g_count[i] = 0.0f;
    if (i == 0) { g_commit = 0.0; g_nsum = 0.0; }
}

__global__ void k_norms(const float* __restrict__ z, const float* __restrict__ emb) {
    int w    = (blockIdx.x * blockDim.x + threadIdx.x) >> 5;
    int lane = threadIdx.x & 31;
    if (w >= NTOK + KCB) return;
    const float4* r4 = (const float4*)((w < NTOK) ? (z + (size_t)w * DIM)
                                                  : (emb + (size_t)(w - NTOK) * DIM));
    double s = 0.0;
#pragma unroll
    for (int i = 0; i < 2; i++) {
        float4 v = r4[lane + 32 * i];
        s += (double)v.x * v.x + (double)v.y * v.y + (double)v.z * v.z + (double)v.w * v.w;
    }
#pragma unroll
    for (int o = 16; o; o >>= 1) s += __shfl_down_sync(0xffffffffu, s, o);
    if (lane == 0) {
        if (w < NTOK) g_zz[w] = (float)s; else g_ww[w - NTOK] = (float)s;
    }
}

// ---------------------------------------------------------------------------
// distance GEMM + fused argmin. f32x2 pairs along N, 16x8 thread tile.
// Group-padded smem layout (stride 36 words per 16-token / 32-code group):
// injective by construction, conflict-free A reads, 2-way-optimal B reads.
// ---------------------------------------------------------------------------
__global__ __launch_bounds__(256, 1)
void k_argmin(const float* __restrict__ z, const float* __restrict__ emb) {
    __shared__ __align__(16) float Ad[2][BKD][AROW];
    __shared__ __align__(16) float Bs[2][BKD][BROW];

    int tid = threadIdx.x;
    int tx = tid & 15, ty = tid >> 4;
    int x = tx * 8, y = ty * 16;
    int m0 = blockIdx.x * BM;

    // staging mapping (injective: max 36*15+30=570<576, 36*3+31=139<144)
    int aw = 36 * (tid >> 4) + 2 * (tid & 15);          // A store word (token tid)
    int nB = tid >> 1;                                  // B row (code)
    int dq = (tid & 1) * 4;                             // B d-quad
    int bw = 36 * (nB >> 5) + (nB & 31);                // B store word
    const float* zrow = z + (size_t)(m0 + tid) * DIM;

    float zzr[16];
#pragma unroll
    for (int i = 0; i < 16; i += 4)
        *(float4*)&zzr[i] = *(const float4*)&g_zz[m0 + y + i];

    float bestv[16]; int besti[16];
#pragma unroll
    for (int i = 0; i < 16; i++) { bestv[i] = __int_as_float(0x7f800000); besti[i] = 0; }

    int arw = 36 * ty;                                  // A read word base
    int brw = 36 * (tx >> 2) + 8 * (tx & 3);            // B read word base

    for (int nt = 0; nt < KCB / BN; ++nt) {
        int n0 = nt * BN;
        const float* brow = emb + (size_t)(n0 + nB) * DIM + dq;

        unsigned long long acc[16][4];
#pragma unroll
        for (int i = 0; i < 16; i++)
#pragma unroll
            for (int j = 0; j < 4; j++) acc[i][j] = 0ULL;

        float4 u = *(const float4*)(zrow);
        float4 v = *(const float4*)(zrow + 4);
        float4 p = *(const float4*)(brow);
        {
            float* A0 = &Ad[0][0][aw];
            *(float2*)(A0 + 0 * AROW) = make_float2(u.x, u.x);
            *(float2*)(A0 + 1 * AROW) = make_float2(u.y, u.y);
            *(float2*)(A0 + 2 * AROW) = make_float2(u.z, u.z);
            *(float2*)(A0 + 3 * AROW) = make_float2(u.w, u.w);
            *(float2*)(A0 + 4 * AROW) = make_float2(v.x, v.x);
            *(float2*)(A0 + 5 * AROW) = make_float2(v.y, v.y);
            *(float2*)(A0 + 6 * AROW) = make_float2(v.z, v.z);
            *(float2*)(A0 + 7 * AROW) = make_float2(v.w, v.w);
            float* B0 = &Bs[0][dq][bw];
            B0[0 * BROW] = p.x; B0[1 * BROW] = p.y;
            B0[2 * BROW] = p.z; B0[3 * BROW] = p.w;
        }
        __syncthreads();

        for (int kt = 0; kt < DIM / BKD; ++kt) {
            int cur = kt & 1;
            if (kt + 1 < DIM / BKD) {
                int db = (kt + 1) * BKD;
                u = *(const float4*)(zrow + db);
                v = *(const float4*)(zrow + db + 4);
                p = *(const float4*)(brow + db);
            }
#pragma unroll
            for (int d = 0; d < BKD; ++d) {
                const float* ar = &Ad[cur][d][arw];
                const float* br = &Bs[cur][d][brw];
                unsigned long long a2[16], b2[4];
#pragma unroll
                for (int i = 0; i < 8; i++) {
                    ulonglong2 t = *(const ulonglong2*)(ar + 4 * i);
                    a2[2 * i] = t.x; a2[2 * i + 1] = t.y;
                }
#pragma unroll
                for (int j = 0; j < 2; j++) {
                    ulonglong2 t = *(const ulonglong2*)(br + 4 * j);
                    b2[2 * j] = t.x; b2[2 * j + 1] = t.y;
                }
#pragma unroll
                for (int i = 0; i < 16; i++)
#pragma unroll
                    for (int j = 0; j < 4; j++)
                        asm("fma.rn.f32x2 %0, %1, %2, %0;"
                            : "+l"(acc[i][j]) : "l"(a2[i]), "l"(b2[j]));
            }
            if (kt + 1 < DIM / BKD) {
                int nx = (kt + 1) & 1;
                float* A0 = &Ad[nx][0][aw];
                *(float2*)(A0 + 0 * AROW) = make_float2(u.x, u.x);
                *(float2*)(A0 + 1 * AROW) = make_float2(u.y, u.y);
                *(float2*)(A0 + 2 * AROW) = make_float2(u.z, u.z);
                *(float2*)(A0 + 3 * AROW) = make_float2(u.w, u.w);
                *(float2*)(A0 + 4 * AROW) = make_float2(v.x, v.x);
                *(float2*)(A0 + 5 * AROW) = make_float2(v.y, v.y);
                *(float2*)(A0 + 6 * AROW) = make_float2(v.z, v.z);
                *(float2*)(A0 + 7 * AROW) = make_float2(v.w, v.w);
                float* B0 = &Bs[nx][dq][bw];
                B0[0 * BROW] = p.x; B0[1 * BROW] = p.y;
                B0[2 * BROW] = p.z; B0[3 * BROW] = p.w;
            }
            __syncthreads();
        }

        // epilogue: dist = (zz - 2*dot) + ww, ascending n, strict <
        float wwv[8];
        *(float4*)&wwv[0] = *(const float4*)&g_ww[n0 + x];
        *(float4*)&wwv[4] = *(const float4*)&g_ww[n0 + x + 4];
#pragma unroll
        for (int i = 0; i < 16; i++)
#pragma unroll
            for (int j = 0; j < 4; j++) {
                float lo = __uint_as_float((unsigned)(acc[i][j] & 0xffffffffULL));
                float hi = __uint_as_float((unsigned)(acc[i][j] >> 32));
                float dl = (zzr[i] - 2.0f * lo) + wwv[2 * j];
                float dh = (zzr[i] - 2.0f * hi) + wwv[2 * j + 1];
                if (dl < bestv[i]) { bestv[i] = dl; besti[i] = n0 + x + 2 * j; }
                if (dh < bestv[i]) { bestv[i] = dh; besti[i] = n0 + x + 2 * j + 1; }
            }
    }

#pragma unroll
    for (int i = 0; i < 16; i++) {
        float v = bestv[i]; int ix = besti[i];
#pragma unroll
        for (int o = 8; o; o >>= 1) {
            float ov = __shfl_down_sync(0xffffffffu, v, o, 16);
            int   oi = __shfl_down_sync(0xffffffffu, ix, o, 16);
            if (ov < v || (ov == v && oi < ix)) { v = ov; ix = oi; }
        }
        if (tx == 0) g_idx[m0 + y + i] = ix;
    }
}

__global__ void k_scatter(const float* __restrict__ z, const float* __restrict__ emb,
                          float* __restrict__ out) {
    int row  = blockIdx.x * 8 + (threadIdx.x >> 5);
    int lane = threadIdx.x & 31;
    int k = g_idx[row];
    const float4* zr = (const float4*)(z   + (size_t)row * DIM);
    const float4* wr = (const float4*)(emb + (size_t)k  * DIM);
    float4*       oq = (float4*)(out + (size_t)row * DIM);

    float cs = 0.0f;
#pragma unroll
    for (int h = 0; h < 2; h++) {
        int c = lane + 32 * h;
        float4 zv = zr[c];
        float4 wv = wr[c];
        float4 o;
        o.x = zv.x + (wv.x - zv.x);
        o.y = zv.y + (wv.y - zv.y);
        o.z = zv.z + (wv.z - zv.z);
        o.w = zv.w + (wv.w - zv.w);
        oq[c] = o;
        float dx = zv.x - wv.x, dy = zv.y - wv.y, dz = zv.z - wv.z, dw = zv.w - wv.w;
        cs += dx * dx + dy * dy + dz * dz + dw * dw;
        float* ar = &g_avg[(size_t)k * DIM + 4 * c];
        atomicAdd(ar + 0, zv.x); atomicAdd(ar + 1, zv.y);
        atomicAdd(ar + 2, zv.z); atomicAdd(ar + 3, zv.w);
    }
#pragma unroll
    for (int o = 16; o; o >>= 1) cs += __shfl_down_sync(0xffffffffu, cs, o);

    __shared__ float sred[8];
    if (lane == 0) {
        sred[threadIdx.x >> 5] = cs;
        atomicAdd(&g_count[k], 1.0f);
        out[(size_t)NTOK * DIM + 1 + row] = (float)k;
    }
    __syncthreads();
    if (threadIdx.x == 0) {
        double bs = 0.0;
#pragma unroll
        for (int i = 0; i < 8; i++) bs += (double)sred[i];
        atomicAdd(&g_commit, bs);
    }
}

__global__ void k_nsum(const float* __restrict__ ema_count) {
    __shared__ double sd[1024];
    int t = threadIdx.x;
    double s = 0.0;
    for (int k = t; k < KCB; k += 1024)
        s += (double)(0.99f * ema_count[k] + 0.01f * g_count[k]);
    sd[t] = s;
    __syncthreads();
    for (int o = 512; o; o >>= 1) {
        if (t < o) sd[t] += sd[t + o];
        __syncthreads();
    }
    if (t == 0) g_nsum = sd[0];
}

__global__ void k_final(const float* __restrict__ ema_count,
                        const float* __restrict__ ema_avg,
                        float* __restrict__ out) {
    size_t i = (size_t)blockIdx.x * 256 + threadIdx.x;
    if (i >= (size_t)KCB * DIM) return;
    int k = (int)(i >> 8);
    float cnt = 0.99f * ema_count[k] + 0.01f * g_count[k];
    float avg = 0.99f * ema_avg[i]   + 0.01f * g_avg[i];
    float nn  = (float)g_nsum;
    float cluster = (cnt + 1e-5f) / (nn + 0.08192f) * nn;
    const size_t oE = (size_t)NTOK * DIM + 1 + NTOK;
    const size_t oC = oE + (size_t)KCB * DIM;
    const size_t oA = oC + KCB;
    out[oE + i] = avg / cluster;
    out[oA + i] = avg;
    if ((i & 255) == 0) out[oC + k] = cnt;
    if (i == 0)
        out[(size_t)NTOK * DIM] =
            (float)(0.25 * g_commit / (double)((size_t)NTOK * DIM));
}

extern "C" void kernel_launch(void* const* d_in, const int* in_sizes, int n_in,
                              void* d_out, int out_size) {
    const float* z_e       = (const float*)d_in[0];
    const float* embedding = (const float*)d_in[1];
    const float* ema_count = (const float*)d_in[2];
    const float* ema_avg   = (const float*)d_in[3];
    float* out = (float*)d_out;

    k_init_a<<<(KCB * DIM + 255) / 256, 256>>>();
    k_init_b<<<(KCB + 255) / 256, 256>>>();
    k_norms<<<(NTOK + KCB) / 8, 256>>>(z_e, embedding);
    k_argmin<<<NTOK / BM, 256>>>(z_e, embedding);   // 4th launch -> profiled slot
    k_scatter<<<NTOK / 8, 256>>>(z_e, embedding, out);
    k_nsum<<<1, 1024>>>(ema_count);
    k_final<<<(KCB * DIM + 255) / 256, 256>>>(ema_count, ema_avg, out);
}